// round 5
// baseline (speedup 1.0000x reference)
#include <cuda_runtime.h>
#include <cuda_bf16.h>
#include <math.h>

// Problem constants
#define B_  256
#define T_  512
#define I_  128
#define H_  512
#define O_  64
#define ALPHA 0.2f
#define BETA_ 8.0f
#define THRESH 20.0f

// Scratch (device globals; no runtime allocation)
__device__ float g_xw[(size_t)B_ * T_ * H_];       // 268 MB: xw, then overwritten with h states
__device__ float g_WhhT[H_ * H_];                  // W_hh^T  [k][j]
__device__ float g_WxhT[I_ * H_];                  // W_xh^T  [i][h]
__device__ float g_WoutT[H_ * O_];                 // W_out^T [k][o]

// ---------------------------------------------------------------------------
// Transpose: in[R][C] -> out[C][R]
// ---------------------------------------------------------------------------
__global__ void transpose_kernel(const float* __restrict__ in, float* __restrict__ out,
                                 int R, int C) {
    int idx = blockIdx.x * blockDim.x + threadIdx.x;
    if (idx < R * C) {
        int r = idx / C;
        int c = idx % C;
        out[c * R + r] = in[idx];
    }
}

// ---------------------------------------------------------------------------
// Tiled SGEMM: C[M,N] = A[M,K] * B[K,N] (+ bias[N])
// 64x64 tile, BK=32, 256 threads, 4x4 microtile per thread.
// ---------------------------------------------------------------------------
__global__ __launch_bounds__(256) void sgemm64(const float* __restrict__ A,
                                               const float* __restrict__ Bm,
                                               const float* __restrict__ bias,
                                               float* __restrict__ C,
                                               int M, int N, int K) {
    __shared__ float As[32][65];
    __shared__ float Bs[32][64];

    int tid = threadIdx.x;
    int m0 = blockIdx.x * 64;
    int n0 = blockIdx.y * 64;
    int tx = tid % 16;        // N direction (4 cols each)
    int ty = tid / 16;        // M direction (4 rows each)

    int a_k = tid % 32;       // k within A tile
    int a_m = tid / 32;       // row group, stride 8
    int b_n = tid % 64;
    int b_k = tid / 64;       // stride 4

    float acc[4][4];
#pragma unroll
    for (int i = 0; i < 4; i++)
#pragma unroll
        for (int j = 0; j < 4; j++) acc[i][j] = 0.0f;

    for (int k0 = 0; k0 < K; k0 += 32) {
#pragma unroll
        for (int i = 0; i < 8; i++)
            As[a_k][a_m + 8 * i] = A[(size_t)(m0 + a_m + 8 * i) * K + (k0 + a_k)];
#pragma unroll
        for (int i = 0; i < 8; i++)
            Bs[b_k + 4 * i][b_n] = Bm[(size_t)(k0 + b_k + 4 * i) * N + (n0 + b_n)];
        __syncthreads();

#pragma unroll
        for (int kk = 0; kk < 32; kk++) {
            float a[4], b[4];
#pragma unroll
            for (int i = 0; i < 4; i++) a[i] = As[kk][ty * 4 + i];
#pragma unroll
            for (int j = 0; j < 4; j++) b[j] = Bs[kk][tx * 4 + j];
#pragma unroll
            for (int i = 0; i < 4; i++)
#pragma unroll
                for (int j = 0; j < 4; j++) acc[i][j] += a[i] * b[j];
        }
        __syncthreads();
    }

#pragma unroll
    for (int i = 0; i < 4; i++) {
        size_t row = (size_t)(m0 + ty * 4 + i);
#pragma unroll
        for (int j = 0; j < 4; j++) {
            int col = n0 + tx * 4 + j;
            float v = acc[i][j];
            if (bias) v += bias[col];
            C[row * N + col] = v;
        }
    }
}

// ---------------------------------------------------------------------------
// phi: F.softplus(x, beta=8, threshold=20)
// ---------------------------------------------------------------------------
__device__ __forceinline__ float phi_fn(float x) {
    float z = BETA_ * x;
    if (z > THRESH) return x;
    return log1pf(expf(z)) * (1.0f / BETA_);
}

// ---------------------------------------------------------------------------
// Recurrence: each block owns 2 batch rows for all T steps.
// Thread j owns hidden column j. h kept in SMEM (broadcast reads),
// W_hh^T streamed from L2 (coalesced along j).
// g_xw is read (xw_t) and overwritten in place with h_t.
// ---------------------------------------------------------------------------
__global__ __launch_bounds__(512) void recurrence_kernel(const float* __restrict__ WhhT,
                                                         float* __restrict__ xw) {
    int j = threadIdx.x;              // 0..511
    int b0 = blockIdx.x * 2;
    int b1 = b0 + 1;

    __shared__ float hs0[H_];
    __shared__ float hs1[H_];
    hs0[j] = 0.0f;
    hs1[j] = 0.0f;
    __syncthreads();

    for (int t = 0; t < T_; t++) {
        float* xw0 = &xw[((size_t)b0 * T_ + t) * H_];
        float* xw1 = &xw[((size_t)b1 * T_ + t) * H_];
        float acc0 = xw0[j];          // already includes b_h (fused as GEMM bias)
        float acc1 = xw1[j];

        const float* wp = WhhT + j;
#pragma unroll 16
        for (int k = 0; k < H_; k++) {
            float w = wp[(size_t)k * H_];
            acc0 += hs0[k] * w;
            acc1 += hs1[k] * w;
        }

        float h0 = (1.0f - ALPHA) * hs0[j] + ALPHA * phi_fn(acc0);
        float h1 = (1.0f - ALPHA) * hs1[j] + ALPHA * phi_fn(acc1);
        __syncthreads();
        hs0[j] = h0;
        hs1[j] = h1;
        xw0[j] = h0;                  // stash h_t for the readout GEMM
        xw1[j] = h1;
        __syncthreads();
    }
}

// ---------------------------------------------------------------------------
// kernel_launch
// inputs (metadata order): x[B,T,I], W_xh[H,I], W_hh[H,H], b_h[H], W_out[O,H], b_out[O]
// output: float [B,T,O]
// ---------------------------------------------------------------------------
extern "C" void kernel_launch(void* const* d_in, const int* in_sizes, int n_in,
                              void* d_out, int out_size) {
    const float* x     = (const float*)d_in[0];
    const float* W_xh  = (const float*)d_in[1];
    const float* W_hh  = (const float*)d_in[2];
    const float* b_h   = (const float*)d_in[3];
    const float* W_out = (const float*)d_in[4];
    const float* b_out = (const float*)d_in[5];
    float* out = (float*)d_out;

    float *xw_p, *whhT_p, *wxhT_p, *woutT_p;
    cudaGetSymbolAddress((void**)&xw_p,   g_xw);
    cudaGetSymbolAddress((void**)&whhT_p, g_WhhT);
    cudaGetSymbolAddress((void**)&wxhT_p, g_WxhT);
    cudaGetSymbolAddress((void**)&woutT_p, g_WoutT);

    // 1) transposes
    transpose_kernel<<<(H_ * I_ + 255) / 256, 256>>>(W_xh, wxhT_p, H_, I_);
    transpose_kernel<<<(H_ * H_ + 255) / 256, 256>>>(W_hh, whhT_p, H_, H_);
    transpose_kernel<<<(O_ * H_ + 255) / 256, 256>>>(W_out, woutT_p, O_, H_);

    // 2) xw = x @ W_xh^T + b_h   -> g_xw  [B*T, H]
    {
        dim3 grid((B_ * T_) / 64, H_ / 64);
        sgemm64<<<grid, 256>>>(x, wxhT_p, b_h, xw_p, B_ * T_, H_, I_);
    }

    // 3) recurrence (overwrites g_xw with h states)
    recurrence_kernel<<<B_ / 2, 512>>>(whhT_p, xw_p);

    // 4) y = h @ W_out^T + b_out -> d_out [B*T, O]
    {
        dim3 grid((B_ * T_) / 64, O_ / 64);
        sgemm64<<<grid, 256>>>(xw_p, woutT_p, b_out, out, B_ * T_, O_, H_);
    }
}